// round 3
// baseline (speedup 1.0000x reference)
#include <cuda_runtime.h>
#include <cstdint>
#include <math.h>

// Problem dims (fixed by the reference)
#define BB   64
#define SS   4096
#define DECD 512
#define ENCD 1024
#define AD   256
#define NEG_INF_F (-1e10f)

// ---------------- scratch (no allocations allowed) ----------------
__device__ float g_dec_proj[BB * AD];                 // (B, A)
__device__ float g_scores[BB * SS];                   // (B, S)
__device__ __align__(16) float g_ctx_part[8 * BB * ENCD];  // (chunk, B, ENC)
__device__ int   g_mask_is_u8;                        // 1 = packed uint8 bools, 0 = int32

// ---------------- f32x2 packed-FMA helpers (B300 FFMA2 path) ----------------
__device__ __forceinline__ unsigned long long fma2(unsigned long long a,
                                                   unsigned long long b,
                                                   unsigned long long c) {
    unsigned long long d;
    asm("fma.rn.f32x2 %0, %1, %2, %3;" : "=l"(d) : "l"(a), "l"(b), "l"(c));
    return d;
}
__device__ __forceinline__ unsigned long long dup2(float x) {
    unsigned long long d;
    asm("mov.b64 %0, {%1, %1};" : "=l"(d) : "f"(x));
    return d;
}
__device__ __forceinline__ float2 unpk2(unsigned long long x) {
    float2 r;
    asm("mov.b64 {%0, %1}, %2;" : "=f"(r.x), "=f"(r.y) : "l"(x));
    return r;
}

// ---------------- kernel 0: detect mask dtype ----------------
// If the mask buffer is int32 (bool promoted), every 32-bit word is 0 or 1.
// If it is packed uint8 bools, random words exceed 1 with overwhelming
// probability (P[all 1024 words <= 1] = (1/8)^1024). 4KB scan is in-bounds
// for both layouts (uint8 buffer = 256KB).
__global__ void k_detect_mask(const unsigned int* __restrict__ m) {
    unsigned int v = m[threadIdx.x];           // 1024 threads
    int any = __syncthreads_or(v > 1u);
    if (threadIdx.x == 0) g_mask_is_u8 = any;
}

// ---------------- kernel 1: dec_proj = decoder_hidden @ W_dec ----------------
__global__ void k_dec_proj(const float* __restrict__ dh,
                           const float* __restrict__ Wd) {
    int b = blockIdx.x;
    int a = threadIdx.x;            // 256 threads, one per A column
    const float* dhb = dh + b * DECD;
    float acc = 0.f;
#pragma unroll 8
    for (int d = 0; d < DECD; d++)
        acc = fmaf(dhb[d], Wd[d * AD + a], acc);
    g_dec_proj[b * AD + a] = acc;
}

// ---------------- kernel 2: scores = v . tanh(dec_proj + E @ W_enc) ----------------
// Block: 64 S-rows x 256 A-cols for one batch. 256 threads, thread tile 4x16 (8 f32x2 pairs).
__global__ __launch_bounds__(256, 2) void k_scores(const float* __restrict__ enc,
                                                   const float* __restrict__ We,
                                                   const float* __restrict__ v) {
    __shared__ __align__(16) float Es[16][68];    // [k][row], padded stride
    __shared__ __align__(16) float Ws[16][256];   // [k][col]

    const int tid = threadIdx.x;
    const int b = blockIdx.y;
    const int s0 = blockIdx.x * 64;
    const int tx = tid & 15;
    const int ty = tid >> 4;
    const int r0 = ty * 4;         // 4 rows
    const int c0 = tx * 16;        // 16 cols (8 pairs)

    const float* Eb = enc + ((size_t)b * SS + s0) * ENCD;

    unsigned long long acc[4][8];
#pragma unroll
    for (int j = 0; j < 4; j++)
#pragma unroll
        for (int p = 0; p < 8; p++) acc[j][p] = 0ull;

    const int er = tid >> 2;           // 0..63 row for E load
    const int ecg = (tid & 3) * 4;     // 0,4,8,12 col group

    for (int k0 = 0; k0 < ENCD; k0 += 16) {
        // load E tile (64x16)
        float4 ev = *(const float4*)(Eb + (size_t)er * ENCD + k0 + ecg);
        Es[ecg + 0][er] = ev.x;
        Es[ecg + 1][er] = ev.y;
        Es[ecg + 2][er] = ev.z;
        Es[ecg + 3][er] = ev.w;
        // load W tile (16x256)
#pragma unroll
        for (int i = 0; i < 4; i++) {
            int idx = tid + i * 256;
            int wr = idx >> 6;
            int wc = (idx & 63) * 4;
            *(float4*)(&Ws[wr][wc]) = *(const float4*)(We + (size_t)(k0 + wr) * AD + wc);
        }
        __syncthreads();

#pragma unroll
        for (int k = 0; k < 16; k++) {
            float4 e4 = *(const float4*)(&Es[k][r0]);
            unsigned long long e2[4];
            e2[0] = dup2(e4.x); e2[1] = dup2(e4.y);
            e2[2] = dup2(e4.z); e2[3] = dup2(e4.w);

            ulonglong2 wA = *(const ulonglong2*)(&Ws[k][c0]);
            ulonglong2 wB = *(const ulonglong2*)(&Ws[k][c0 + 4]);
            ulonglong2 wC = *(const ulonglong2*)(&Ws[k][c0 + 8]);
            ulonglong2 wD = *(const ulonglong2*)(&Ws[k][c0 + 12]);
            unsigned long long wp[8] = {wA.x, wA.y, wB.x, wB.y, wC.x, wC.y, wD.x, wD.y};

#pragma unroll
            for (int j = 0; j < 4; j++)
#pragma unroll
                for (int p = 0; p < 8; p++)
                    acc[j][p] = fma2(e2[j], wp[p], acc[j][p]);
        }
        __syncthreads();
    }

    // epilogue: score partial = sum over this thread's 16 cols of v[c]*tanh(dp[c]+acc)
    const float* dpb = g_dec_proj + b * AD;
    float dp[16], vv[16];
#pragma unroll
    for (int i = 0; i < 16; i++) {
        dp[i] = dpb[c0 + i];
        vv[i] = v[c0 + i];
    }

#pragma unroll
    for (int j = 0; j < 4; j++) {
        float part = 0.f;
#pragma unroll
        for (int p = 0; p < 8; p++) {
            float2 t = unpk2(acc[j][p]);
            part += vv[2 * p]     * tanhf(dp[2 * p]     + t.x);
            part += vv[2 * p + 1] * tanhf(dp[2 * p + 1] + t.y);
        }
        // reduce across the 16 tx lanes (lanes differ only in low 4 bits)
#pragma unroll
        for (int m = 8; m; m >>= 1)
            part += __shfl_xor_sync(0xffffffffu, part, m);
        if (tx == 0) {
            int s = s0 + r0 + j;
            g_scores[(size_t)b * SS + s] = part;
        }
    }
}

// ---------------- kernel 3: mask + softmax over S per batch ----------------
__global__ __launch_bounds__(256) void k_softmax(const void* __restrict__ mask,
                                                 float* __restrict__ out_w) {
    const int b = blockIdx.x;
    const int tid = threadIdx.x;
    const float* row = g_scores + (size_t)b * SS;
    const int u8 = g_mask_is_u8;
    const uint8_t* m8 = (const uint8_t*)mask;
    const int*     m32 = (const int*)mask;

    float vals[16];
    float mx = -INFINITY;
#pragma unroll
    for (int i = 0; i < 16; i++) {
        size_t idx = (size_t)b * SS + tid + i * 256;
        int msk = u8 ? (int)m8[idx] : m32[idx];
        vals[i] = msk ? NEG_INF_F : row[tid + i * 256];
        mx = fmaxf(mx, vals[i]);
    }
#pragma unroll
    for (int m = 16; m; m >>= 1)
        mx = fmaxf(mx, __shfl_xor_sync(0xffffffffu, mx, m));
    __shared__ float redm[8];
    if ((tid & 31) == 0) redm[tid >> 5] = mx;
    __syncthreads();
    mx = redm[0];
#pragma unroll
    for (int i = 1; i < 8; i++) mx = fmaxf(mx, redm[i]);

    float sum = 0.f;
#pragma unroll
    for (int i = 0; i < 16; i++) {
        vals[i] = expf(vals[i] - mx);
        sum += vals[i];
    }
#pragma unroll
    for (int m = 16; m; m >>= 1)
        sum += __shfl_xor_sync(0xffffffffu, sum, m);
    __shared__ float reds[8];
    if ((tid & 31) == 0) reds[tid >> 5] = sum;
    __syncthreads();
    sum = 0.f;
#pragma unroll
    for (int i = 0; i < 8; i++) sum += reds[i];

    float inv = 1.f / sum;
#pragma unroll
    for (int i = 0; i < 16; i++)
        out_w[(size_t)b * SS + tid + i * 256] = vals[i] * inv;
}

// ---------------- kernel 4: context partials over S-chunks (deterministic) ----------------
__global__ __launch_bounds__(256) void k_context_part(const float* __restrict__ enc,
                                                      const float* __restrict__ w) {
    const int chunk = blockIdx.x;   // 0..7 (512 S-rows each)
    const int b = blockIdx.y;
    const int tid = threadIdx.x;
    const int s0 = chunk * 512;

    __shared__ float ws[512];
    ws[tid]       = w[(size_t)b * SS + s0 + tid];
    ws[tid + 256] = w[(size_t)b * SS + s0 + tid + 256];
    __syncthreads();

    const float* Eb = enc + ((size_t)b * SS + s0) * ENCD;
    const int e0 = tid * 4;   // 256 threads x float4 covers ENC=1024

    float4 acc = make_float4(0.f, 0.f, 0.f, 0.f);
#pragma unroll 4
    for (int s = 0; s < 512; s++) {
        float wv = ws[s];
        float4 x = *(const float4*)(Eb + (size_t)s * ENCD + e0);
        acc.x = fmaf(wv, x.x, acc.x);
        acc.y = fmaf(wv, x.y, acc.y);
        acc.z = fmaf(wv, x.z, acc.z);
        acc.w = fmaf(wv, x.w, acc.w);
    }
    *(float4*)(g_ctx_part + ((size_t)chunk * BB + b) * ENCD + e0) = acc;
}

// ---------------- kernel 5: reduce partials -> context ----------------
__global__ void k_context_reduce(float* __restrict__ out_ctx) {
    int i = blockIdx.x * 256 + threadIdx.x;   // 0 .. B*ENC-1
    float acc = 0.f;
#pragma unroll
    for (int c = 0; c < 8; c++)
        acc += g_ctx_part[(size_t)c * BB * ENCD + i];
    out_ctx[i] = acc;
}

// ---------------- launch ----------------
extern "C" void kernel_launch(void* const* d_in, const int* in_sizes, int n_in,
                              void* d_out, int out_size) {
    const float* dh   = (const float*)d_in[0];     // (B, DEC)
    const float* enc  = (const float*)d_in[1];     // (B, S, ENC)
    const void*  mask = d_in[2];                   // (B, S) bool (u8 or i32)
    const float* Wd   = (const float*)d_in[3];     // (DEC, A)
    const float* We   = (const float*)d_in[4];     // (ENC, A)
    const float* v    = (const float*)d_in[5];     // (A,)

    float* out     = (float*)d_out;
    float* out_ctx = out;               // (B, ENC) first
    float* out_w   = out + BB * ENCD;   // (B, S) second

    k_detect_mask<<<1, 1024>>>((const unsigned int*)mask);

    k_dec_proj<<<BB, 256>>>(dh, Wd);

    dim3 g2(SS / 64, BB);
    k_scores<<<g2, 256>>>(enc, We, v);

    k_softmax<<<BB, 256>>>(mask, out_w);

    dim3 g4(8, BB);
    k_context_part<<<g4, 256>>>(enc, out_w);

    k_context_reduce<<<(BB * ENCD) / 256, 256>>>(out_ctx);
}

// round 7
// speedup vs baseline: 6.4666x; 6.4666x over previous
#include <cuda_runtime.h>
#include <cuda_bf16.h>
#include <cstdint>
#include <math.h>

// Problem dims (fixed)
#define BB   64
#define SS   4096
#define DECD 512
#define ENCD 1024
#define AD   256
#define NEG_INF_F (-1e10f)

#define CTX_CHUNKS 16
#define CTX_SROWS  (SS / CTX_CHUNKS)   // 256

// ---------------- scratch ----------------
__device__ float g_dec_proj[BB * AD];
__device__ float g_scores[BB * SS];
__device__ __align__(16) float g_ctx_part[CTX_CHUNKS * BB * ENCD];
__device__ int   g_mask_is_u8;
// W_enc split to bf16 hi/lo, [k][n] row-major (k=0..1023, n=0..255)
__device__ __align__(16) __nv_bfloat16 g_w_hi[ENCD * AD];
__device__ __align__(16) __nv_bfloat16 g_w_lo[ENCD * AD];

// ---------------- helpers ----------------
__device__ __forceinline__ uint32_t smem_u32(const void* p) {
    uint32_t a;
    asm("{ .reg .u64 t; cvta.to.shared.u64 t, %1; cvt.u32.u64 %0, t; }" : "=r"(a) : "l"(p));
    return a;
}
__device__ __forceinline__ void ldsm_x4(uint32_t* r, uint32_t addr) {
    asm volatile("ldmatrix.sync.aligned.m8n8.x4.shared.b16 {%0,%1,%2,%3}, [%4];"
        : "=r"(r[0]), "=r"(r[1]), "=r"(r[2]), "=r"(r[3]) : "r"(addr));
}
__device__ __forceinline__ void ldsm_x4t(uint32_t* r, uint32_t addr) {
    asm volatile("ldmatrix.sync.aligned.m8n8.x4.trans.shared.b16 {%0,%1,%2,%3}, [%4];"
        : "=r"(r[0]), "=r"(r[1]), "=r"(r[2]), "=r"(r[3]) : "r"(addr));
}
__device__ __forceinline__ void mma16816(float* d, const uint32_t* a, const uint32_t* b) {
    asm volatile("mma.sync.aligned.m16n8k16.row.col.f32.bf16.bf16.f32 "
        "{%0,%1,%2,%3}, {%4,%5,%6,%7}, {%8,%9}, {%0,%1,%2,%3};"
        : "+f"(d[0]), "+f"(d[1]), "+f"(d[2]), "+f"(d[3])
        : "r"(a[0]), "r"(a[1]), "r"(a[2]), "r"(a[3]), "r"(b[0]), "r"(b[1]));
}
__device__ __forceinline__ uint32_t pkbf(__nv_bfloat16 a, __nv_bfloat16 b) {
    uint16_t ua = *(uint16_t*)&a, ub = *(uint16_t*)&b;
    return (uint32_t)ua | ((uint32_t)ub << 16);
}
// accurate fast tanh via MUFU ex2 (rel err ~1e-6)
__device__ __forceinline__ float tanh_f(float x) {
    float e = __expf(2.0f * x);
    return 1.0f - __fdividef(2.0f, e + 1.0f);
}

// ---------------- kernel 0: detect mask dtype ----------------
__global__ void k_detect_mask(const unsigned int* __restrict__ m) {
    unsigned int v = m[threadIdx.x];
    int any = __syncthreads_or(v > 1u);
    if (threadIdx.x == 0) g_mask_is_u8 = any;
}

// ---------------- kernel 0b: split W_enc into bf16 hi/lo ----------------
__global__ void k_prep_w(const float* __restrict__ We) {
    int k = blockIdx.x;             // 0..1023
    int n = threadIdx.x;            // 0..255
    float x = We[(size_t)k * AD + n];
    __nv_bfloat16 h = __float2bfloat16_rn(x);
    __nv_bfloat16 l = __float2bfloat16_rn(x - __bfloat162float(h));
    g_w_hi[(size_t)k * AD + n] = h;
    g_w_lo[(size_t)k * AD + n] = l;
}

// ---------------- kernel 1: dec_proj ----------------
__global__ void k_dec_proj(const float* __restrict__ dh, const float* __restrict__ Wd) {
    int b = blockIdx.x;
    int a = threadIdx.x;
    const float* dhb = dh + b * DECD;
    float acc = 0.f;
#pragma unroll 8
    for (int d = 0; d < DECD; d++)
        acc = fmaf(dhb[d], Wd[d * AD + a], acc);
    g_dec_proj[b * AD + a] = acc;
}

// ---------------- kernel 2: mma.sync split-bf16 scores GEMM + tanh.v epilogue ----------------
// CTA: 256 threads / 8 warps. Tile M=64 (S-rows) x N=256 (A). Warp tile 32x64.
// Smem strides padded for conflict-free ldmatrix: E rows 80B, W rows 528B.
#define SE_STRIDE 80     // bytes per E row (64 data + 16 pad)
#define SW_STRIDE 528    // bytes per W row (512 data + 16 pad)

__global__ __launch_bounds__(256, 2)
void k_scores_mma(const float* __restrict__ enc, const float* __restrict__ v) {
    __shared__ __align__(16) uint8_t sEh[64 * SE_STRIDE];
    __shared__ __align__(16) uint8_t sEl[64 * SE_STRIDE];
    __shared__ __align__(16) uint8_t sWh[32 * SW_STRIDE];
    __shared__ __align__(16) uint8_t sWl[32 * SW_STRIDE];
    __shared__ float sv[AD], sdp[AD];
    __shared__ float sp[4][64];

    const int tid  = threadIdx.x;
    const int w    = tid >> 5;
    const int lane = tid & 31;
    const int b    = blockIdx.y;
    const int s0   = blockIdx.x * 64;

    const int wm = (w & 1) * 32;     // warp M offset (32 rows)
    const int wn = (w >> 1);         // warp N quarter (64 cols at wn*64)

    sv[tid]  = v[tid];
    sdp[tid] = g_dec_proj[b * AD + tid];

    const float* Eb = enc + ((size_t)b * SS + s0) * ENCD;

    const uint32_t uEh = smem_u32(sEh), uEl = smem_u32(sEl);
    const uint32_t uWh = smem_u32(sWh), uWl = smem_u32(sWl);

    // Precompute per-lane ldmatrix base addresses (ks=0); ks=1 adds fixed deltas.
    const int li = lane >> 3, l7 = lane & 7;
    // A: matrix i -> m += (i&1)*8, k += (i>>1)*8
    uint32_t aOff[2];
#pragma unroll
    for (int mt = 0; mt < 2; mt++) {
        int m = wm + mt * 16 + (li & 1) * 8 + l7;
        int k = (li >> 1) * 8;
        aOff[mt] = m * SE_STRIDE + k * 2;
    }
    // B: matrix i -> k += (i&1)*8, n += (i>>1)*8
    uint32_t bOff[4];
#pragma unroll
    for (int p = 0; p < 4; p++) {
        int k = (li & 1) * 8 + l7;
        int n = wn * 64 + p * 16 + (li >> 1) * 8;
        bOff[p] = k * SW_STRIDE + n * 2;
    }

    float acc[2][8][4];
#pragma unroll
    for (int mt = 0; mt < 2; mt++)
#pragma unroll
        for (int j = 0; j < 8; j++)
#pragma unroll
            for (int r = 0; r < 4; r++) acc[mt][j][r] = 0.f;

    // precomputed load indices
    const int wrow = tid >> 5, wc16 = tid & 31;          // W copy: 4 rows/thread-iter
    const int er = tid >> 3, ecg = (tid & 7) * 4;        // E: row, fp32 col group

#pragma unroll 1
    for (int c = 0; c < 32; c++) {
        const int k0 = c * 32;
        // ---- load W chunk (32 rows x 256 bf16, hi+lo) ----
#pragma unroll
        for (int i = 0; i < 4; i++) {
            int row = wrow + i * 8;
            const uint4* srcH = (const uint4*)(g_w_hi + (size_t)(k0 + row) * AD + wc16 * 8);
            const uint4* srcL = (const uint4*)(g_w_lo + (size_t)(k0 + row) * AD + wc16 * 8);
            *(uint4*)(sWh + row * SW_STRIDE + wc16 * 16) = *srcH;
            *(uint4*)(sWl + row * SW_STRIDE + wc16 * 16) = *srcL;
        }
        // ---- load E chunk (64 rows x 32 fp32 -> bf16 hi/lo) ----
#pragma unroll
        for (int j = 0; j < 2; j++) {
            int r = er + j * 32;
            float4 x = *(const float4*)(Eb + (size_t)r * ENCD + k0 + ecg);
            __nv_bfloat16 h0 = __float2bfloat16_rn(x.x), h1 = __float2bfloat16_rn(x.y);
            __nv_bfloat16 h2 = __float2bfloat16_rn(x.z), h3 = __float2bfloat16_rn(x.w);
            __nv_bfloat16 l0 = __float2bfloat16_rn(x.x - __bfloat162float(h0));
            __nv_bfloat16 l1 = __float2bfloat16_rn(x.y - __bfloat162float(h1));
            __nv_bfloat16 l2 = __float2bfloat16_rn(x.z - __bfloat162float(h2));
            __nv_bfloat16 l3 = __float2bfloat16_rn(x.w - __bfloat162float(h3));
            uint32_t off = r * SE_STRIDE + ecg * 2;
            *(uint2*)(sEh + off) = make_uint2(pkbf(h0, h1), pkbf(h2, h3));
            *(uint2*)(sEl + off) = make_uint2(pkbf(l0, l1), pkbf(l2, l3));
        }
        __syncthreads();

        // ---- compute: 2 k16 steps ----
#pragma unroll
        for (int ks = 0; ks < 2; ks++) {
            const uint32_t dA = ks * 32;                 // +16 k * 2B
            const uint32_t dB = ks * 16 * SW_STRIDE;
            uint32_t AH[2][4], AL[2][4];
#pragma unroll
            for (int mt = 0; mt < 2; mt++) {
                ldsm_x4(AH[mt], uEh + aOff[mt] + dA);
                ldsm_x4(AL[mt], uEl + aOff[mt] + dA);
            }
#pragma unroll
            for (int p = 0; p < 4; p++) {
                uint32_t BH[4], BL[4];
                ldsm_x4t(BH, uWh + bOff[p] + dB);
                ldsm_x4t(BL, uWl + bOff[p] + dB);
#pragma unroll
                for (int mt = 0; mt < 2; mt++) {
#pragma unroll
                    for (int nt = 0; nt < 2; nt++) {
                        float* d = acc[mt][p * 2 + nt];
                        mma16816(d, AH[mt], BH + nt * 2);
                        mma16816(d, AH[mt], BL + nt * 2);
                        mma16816(d, AL[mt], BH + nt * 2);
                    }
                }
            }
        }
        __syncthreads();
    }

    // ---- epilogue: score_m = sum_n v[n] * tanh(dp[n] + D[m][n]) ----
    const int g = lane >> 2, tig = lane & 3;
#pragma unroll
    for (int mt = 0; mt < 2; mt++) {
        float pA = 0.f, pB = 0.f;
#pragma unroll
        for (int j = 0; j < 8; j++) {
            int c0 = wn * 64 + j * 8 + tig * 2;
            float v0 = sv[c0], v1 = sv[c0 + 1];
            float d0 = sdp[c0], d1 = sdp[c0 + 1];
            pA += v0 * tanh_f(d0 + acc[mt][j][0]);
            pA += v1 * tanh_f(d1 + acc[mt][j][1]);
            pB += v0 * tanh_f(d0 + acc[mt][j][2]);
            pB += v1 * tanh_f(d1 + acc[mt][j][3]);
        }
        pA += __shfl_xor_sync(0xffffffffu, pA, 1);
        pA += __shfl_xor_sync(0xffffffffu, pA, 2);
        pB += __shfl_xor_sync(0xffffffffu, pB, 1);
        pB += __shfl_xor_sync(0xffffffffu, pB, 2);
        if (tig == 0) {
            int rA = wm + mt * 16 + g;
            sp[wn][rA]     = pA;
            sp[wn][rA + 8] = pB;
        }
    }
    __syncthreads();
    if (tid < 64) {
        float s = sp[0][tid] + sp[1][tid] + sp[2][tid] + sp[3][tid];
        g_scores[(size_t)b * SS + s0 + tid] = s;
    }
}

// ---------------- kernel 3: mask + softmax ----------------
__global__ __launch_bounds__(256) void k_softmax(const void* __restrict__ mask,
                                                 float* __restrict__ out_w) {
    const int b = blockIdx.x;
    const int tid = threadIdx.x;
    const float* row = g_scores + (size_t)b * SS;
    const int u8 = g_mask_is_u8;
    const uint8_t* m8 = (const uint8_t*)mask;
    const int*     m32 = (const int*)mask;

    float vals[16];
    float mx = -INFINITY;
#pragma unroll
    for (int i = 0; i < 16; i++) {
        size_t idx = (size_t)b * SS + tid + i * 256;
        int msk = u8 ? (int)m8[idx] : m32[idx];
        vals[i] = msk ? NEG_INF_F : row[tid + i * 256];
        mx = fmaxf(mx, vals[i]);
    }
#pragma unroll
    for (int m = 16; m; m >>= 1)
        mx = fmaxf(mx, __shfl_xor_sync(0xffffffffu, mx, m));
    __shared__ float redm[8];
    if ((tid & 31) == 0) redm[tid >> 5] = mx;
    __syncthreads();
    mx = redm[0];
#pragma unroll
    for (int i = 1; i < 8; i++) mx = fmaxf(mx, redm[i]);

    float sum = 0.f;
#pragma unroll
    for (int i = 0; i < 16; i++) {
        vals[i] = expf(vals[i] - mx);
        sum += vals[i];
    }
#pragma unroll
    for (int m = 16; m; m >>= 1)
        sum += __shfl_xor_sync(0xffffffffu, sum, m);
    __shared__ float reds[8];
    if ((tid & 31) == 0) reds[tid >> 5] = sum;
    __syncthreads();
    sum = 0.f;
#pragma unroll
    for (int i = 0; i < 8; i++) sum += reds[i];

    float inv = 1.f / sum;
#pragma unroll
    for (int i = 0; i < 16; i++)
        out_w[(size_t)b * SS + tid + i * 256] = vals[i] * inv;
}

// ---------------- kernel 4: context partials ----------------
__global__ __launch_bounds__(256) void k_context_part(const float* __restrict__ enc,
                                                      const float* __restrict__ w) {
    const int chunk = blockIdx.x;
    const int b = blockIdx.y;
    const int tid = threadIdx.x;
    const int s0 = chunk * CTX_SROWS;

    __shared__ float ws[CTX_SROWS];
    ws[tid] = w[(size_t)b * SS + s0 + tid];
    __syncthreads();

    const float* Eb = enc + ((size_t)b * SS + s0) * ENCD;
    const int e0 = tid * 4;

    float4 acc = make_float4(0.f, 0.f, 0.f, 0.f);
#pragma unroll 4
    for (int s = 0; s < CTX_SROWS; s++) {
        float wv = ws[s];
        float4 x = *(const float4*)(Eb + (size_t)s * ENCD + e0);
        acc.x = fmaf(wv, x.x, acc.x);
        acc.y = fmaf(wv, x.y, acc.y);
        acc.z = fmaf(wv, x.z, acc.z);
        acc.w = fmaf(wv, x.w, acc.w);
    }
    *(float4*)(g_ctx_part + ((size_t)chunk * BB + b) * ENCD + e0) = acc;
}

// ---------------- kernel 5: reduce partials ----------------
__global__ void k_context_reduce(float* __restrict__ out_ctx) {
    int i = blockIdx.x * 256 + threadIdx.x;
    float acc = 0.f;
#pragma unroll
    for (int c = 0; c < CTX_CHUNKS; c++)
        acc += g_ctx_part[(size_t)c * BB * ENCD + i];
    out_ctx[i] = acc;
}

// ---------------- launch ----------------
extern "C" void kernel_launch(void* const* d_in, const int* in_sizes, int n_in,
                              void* d_out, int out_size) {
    const float* dh   = (const float*)d_in[0];
    const float* enc  = (const float*)d_in[1];
    const void*  mask = d_in[2];
    const float* Wd   = (const float*)d_in[3];
    const float* We   = (const float*)d_in[4];
    const float* v    = (const float*)d_in[5];

    float* out     = (float*)d_out;
    float* out_ctx = out;
    float* out_w   = out + BB * ENCD;

    k_detect_mask<<<1, 1024>>>((const unsigned int*)mask);
    k_prep_w<<<ENCD, 256>>>(We);
    k_dec_proj<<<BB, 256>>>(dh, Wd);

    dim3 g2(SS / 64, BB);
    k_scores_mma<<<g2, 256>>>(enc, v);

    k_softmax<<<BB, 256>>>(mask, out_w);

    dim3 g4(CTX_CHUNKS, BB);
    k_context_part<<<g4, 256>>>(enc, out_w);
    k_context_reduce<<<(BB * ENCD) / 256, 256>>>(out_ctx);
}